// round 13
// baseline (speedup 1.0000x reference)
#include <cuda_runtime.h>
#include <math_constants.h>
#include <cstdint>

// Shapes (fixed):
//   word_features  [B, D, T]   = [32, 256, 32]   fp32   d_in[0]
//   image_features [B, Dh,H,W] = [32, 128,128,128] fp32 d_in[1]
//   words_mask     [B, T]      = [32, 32]        int32  d_in[2]
//   W              [Dh, D]     = [128, 256]      fp32   d_in[3]
//   b              [Dh]        = [128]           fp32   d_in[4]
// Outputs: attn [B,Dh,N] at 0, attn_coefficients [B,N,T] at B*Dh*N.
//
// Masked t columns contribute exactly zero; t is compacted per batch
// (JM = Tcp/8, in-CTA ballot). JM<=2 (~57% of batches) runs an 8-pixel-per-
// pair core (1:16 LDS:FFMA2 ratio); JM>=3 runs the proven 4-pixel core twice.

#define B_   32
#define D_   256
#define T_   32
#define DH_  128
#define N_   16384

__device__ float g_values[B_ * DH_ * T_];

// ---------------- packed f32x2 helpers ----------------
__device__ __forceinline__ unsigned long long pk2(float lo, float hi) {
    unsigned long long r;
    asm("mov.b64 %0, {%1, %2};" : "=l"(r) : "f"(lo), "f"(hi));
    return r;
}
__device__ __forceinline__ float2 unpk2(unsigned long long v) {
    float2 f;
    asm("mov.b64 {%0, %1}, %2;" : "=f"(f.x), "=f"(f.y) : "l"(v));
    return f;
}
__device__ __forceinline__ unsigned long long ffma2(unsigned long long a,
                                                    unsigned long long b,
                                                    unsigned long long c) {
    unsigned long long d;
    asm("fma.rn.f32x2 %0, %1, %2, %3;" : "=l"(d) : "l"(a), "l"(b), "l"(c));
    return d;
}
__device__ __forceinline__ unsigned long long add2(unsigned long long a,
                                                   unsigned long long b) {
    unsigned long long d;
    asm("add.rn.f32x2 %0, %1, %2;" : "=l"(d) : "l"(a), "l"(b));
    return d;
}

// ---------------- kernel 1: values = W * wf + b ----------------
#define SW_PAD 264
__global__ __launch_bounds__(256)
void values_kernel(const float* __restrict__ wf,
                   const float* __restrict__ Wm,
                   const float* __restrict__ bias) {
    __shared__ float swf[D_ * T_];
    __shared__ float sW[32 * SW_PAD];
    const int c = blockIdx.x;
    const int b = blockIdx.y;
    const int tid = threadIdx.x;

    {
        const float4* src =
            reinterpret_cast<const float4*>(wf + (size_t)b * D_ * T_);
        float4* dst = reinterpret_cast<float4*>(swf);
#pragma unroll
        for (int i = 0; i < 8; i++) dst[tid + 256 * i] = src[tid + 256 * i];

        const float4* wsrc =
            reinterpret_cast<const float4*>(Wm + (size_t)c * 32 * D_);
#pragma unroll
        for (int i = 0; i < 8; i++) {
            const int idx = tid + 256 * i;
            const int kl = idx >> 6;
            const int dc = idx & 63;
            float4 v = wsrc[idx];
            *reinterpret_cast<float4*>(&sW[kl * SW_PAD + dc * 4]) = v;
        }
    }
    __syncthreads();

    const int k_l = tid >> 3;
    const int tq = tid & 7;
    const int k = c * 32 + k_l;

    const float bk = bias[k];
    unsigned long long acc0 = pk2(bk, bk);
    unsigned long long acc1 = pk2(bk, bk);

#pragma unroll 4
    for (int d = 0; d < D_; d++) {
        const float w = sW[k_l * SW_PAD + d];
        const unsigned long long wp = pk2(w, w);
        const ulonglong2 v =
            *reinterpret_cast<const ulonglong2*>(&swf[d * T_ + tq * 4]);
        acc0 = ffma2(wp, v.x, acc0);
        acc1 = ffma2(wp, v.y, acc1);
    }

    ulonglong2 o;
    o.x = acc0;
    o.y = acc1;
    *reinterpret_cast<ulonglong2*>(
        g_values + ((size_t)b * DH_ + k) * T_ + tq * 4) = o;
}

// ---------------- P=4 core (JM 3..4), as in R11 ----------------
template <int JM>
__device__ __forceinline__ void attn_core4(
    const ulonglong2* __restrict__ svals,
    const float* __restrict__ scs,
    const int* __restrict__ stl,
    const float4* __restrict__ qb,
    float* __restrict__ ocb,
    float* __restrict__ oa,
    const int half) {
    constexpr int NJ = 2 * JM;
    const int cb = half * 4 * JM;

    unsigned long long acc[4][NJ];
#pragma unroll
    for (int px = 0; px < 4; px++)
#pragma unroll
        for (int j = 0; j < NJ; j++) acc[px][j] = 0ULL;

    float4 qv[4];
#pragma unroll
    for (int kk = 0; kk < 4; kk++) qv[kk] = qb[(size_t)kk * (N_ / 4)];

    for (int k = 0; k < DH_; k += 4) {
        float4 qn[4];
        if (k + 4 < DH_) {
#pragma unroll
            for (int kk = 0; kk < 4; kk++)
                qn[kk] = qb[(size_t)(k + 4 + kk) * (N_ / 4)];
        }
#pragma unroll
        for (int kk = 0; kk < 4; kk++) {
            const unsigned long long q0 = pk2(qv[kk].x, qv[kk].x);
            const unsigned long long q1 = pk2(qv[kk].y, qv[kk].y);
            const unsigned long long q2 = pk2(qv[kk].z, qv[kk].z);
            const unsigned long long q3 = pk2(qv[kk].w, qv[kk].w);
            const ulonglong2* vr = &svals[(size_t)(k + kk) * 8 + half * JM];
#pragma unroll
            for (int j = 0; j < JM; j++) {
                const ulonglong2 v = vr[j];
                acc[0][2 * j + 0] = ffma2(q0, v.x, acc[0][2 * j + 0]);
                acc[0][2 * j + 1] = ffma2(q0, v.y, acc[0][2 * j + 1]);
                acc[1][2 * j + 0] = ffma2(q1, v.x, acc[1][2 * j + 0]);
                acc[1][2 * j + 1] = ffma2(q1, v.y, acc[1][2 * j + 1]);
                acc[2][2 * j + 0] = ffma2(q2, v.x, acc[2][2 * j + 0]);
                acc[2][2 * j + 1] = ffma2(q2, v.y, acc[2][2 * j + 1]);
                acc[3][2 * j + 0] = ffma2(q3, v.x, acc[3][2 * j + 0]);
                acc[3][2 * j + 1] = ffma2(q3, v.y, acc[3][2 * j + 1]);
            }
        }
#pragma unroll
        for (int kk = 0; kk < 4; kk++) qv[kk] = qn[kk];
    }

#pragma unroll
    for (int px = 0; px < 4; px++) {
        float4* z = reinterpret_cast<float4*>(ocb + px * T_ + half * 16);
#pragma unroll
        for (int j = 0; j < 4; j++) z[j] = make_float4(0.f, 0.f, 0.f, 0.f);
    }

#pragma unroll
    for (int px = 0; px < 4; px++) {
        const unsigned long long* snp =
            reinterpret_cast<const unsigned long long*>(&scs[cb]);
        float Sv[2 * NJ];
#pragma unroll
        for (int j = 0; j < NJ; j++) {
            const float2 f = unpk2(add2(acc[px][j], snp[j]));
            Sv[2 * j + 0] = f.x;
            Sv[2 * j + 1] = f.y;
        }
        float m = -CUDART_INF_F;
#pragma unroll
        for (int i = 0; i < 2 * NJ; i++) m = fmaxf(m, Sv[i]);
        m = fmaxf(m, __shfl_xor_sync(0xffffffffu, m, 1));
        float sum = 0.f;
#pragma unroll
        for (int i = 0; i < 2 * NJ; i++) {
            Sv[i] = __expf(Sv[i] - m);
            sum += Sv[i];
        }
        sum += __shfl_xor_sync(0xffffffffu, sum, 1);
        const float inv = 1.0f / sum;
#pragma unroll
        for (int i = 0; i < 2 * NJ; i++) Sv[i] *= inv;
#pragma unroll
        for (int j = 0; j < NJ; j++)
            acc[px][j] = pk2(Sv[2 * j], Sv[2 * j + 1]);
    }

    __syncwarp();
#pragma unroll
    for (int px = 0; px < 4; px++) {
        float* oc = ocb + px * T_;
#pragma unroll
        for (int j = 0; j < NJ; j++) {
            const float2 f = unpk2(acc[px][j]);
            oc[stl[cb + 2 * j + 0]] = f.x;
            oc[stl[cb + 2 * j + 1]] = f.y;
        }
    }

    for (int k = 0; k < DH_; k += 4) {
        unsigned long long mine[4], sent[4];
#pragma unroll
        for (int kk = 0; kk < 4; kk++) {
            const ulonglong2* vr = &svals[(size_t)(k + kk) * 8 + half * JM];
            unsigned long long a0 = 0ULL, a1 = 0ULL, a2 = 0ULL, a3 = 0ULL;
#pragma unroll
            for (int j = 0; j < JM; j++) {
                const ulonglong2 v = vr[j];
                a0 = ffma2(v.x, acc[0][2 * j + 0], a0);
                a0 = ffma2(v.y, acc[0][2 * j + 1], a0);
                a1 = ffma2(v.x, acc[1][2 * j + 0], a1);
                a1 = ffma2(v.y, acc[1][2 * j + 1], a1);
                a2 = ffma2(v.x, acc[2][2 * j + 0], a2);
                a2 = ffma2(v.y, acc[2][2 * j + 1], a2);
                a3 = ffma2(v.x, acc[3][2 * j + 0], a3);
                a3 = ffma2(v.y, acc[3][2 * j + 1], a3);
            }
            const float2 f0 = unpk2(a0), f1 = unpk2(a1);
            const float2 f2 = unpk2(a2), f3 = unpk2(a3);
            const unsigned long long p01 = pk2(f0.x + f0.y, f1.x + f1.y);
            const unsigned long long p23 = pk2(f2.x + f2.y, f3.x + f3.y);
            sent[kk] = half ? p01 : p23;
            mine[kk] = half ? p23 : p01;
        }
        unsigned long long got[4];
#pragma unroll
        for (int kk = 0; kk < 4; kk++)
            got[kk] = __shfl_xor_sync(0xffffffffu, sent[kk], 1);
#pragma unroll
        for (int kk = 0; kk < 4; kk++) {
            const float2 r = unpk2(add2(mine[kk], got[kk]));
            *reinterpret_cast<float2*>(oa + (size_t)(k + kk) * N_) =
                make_float2(r.x, r.y);
        }
    }
}

// ---------------- P=8 core (JM 1..2): 8 pixels per lane pair ----------------
template <int JM>
__device__ __forceinline__ void attn_core8(
    const ulonglong2* __restrict__ svals,
    const float* __restrict__ scs,
    const int* __restrict__ stl,
    const float4* __restrict__ qb,   // img + b*Dh*N + n0, as float4*
    float* __restrict__ ocb,         // out_coef + (b*N+n0)*T_
    float* __restrict__ oa,          // out_attn + b*Dh*N + n0 + 4*half
    const int half) {
    constexpr int NJ = 2 * JM;
    const int cb = half * 4 * JM;

    unsigned long long acc[8][NJ];
#pragma unroll
    for (int px = 0; px < 8; px++)
#pragma unroll
        for (int j = 0; j < NJ; j++) acc[px][j] = 0ULL;

    // ---- phase 1 ----
    float4 qA0 = qb[0], qA1 = qb[1];
    for (int k = 0; k < DH_; k++) {
        float4 qB0, qB1;
        if (k + 1 < DH_) {
            qB0 = qb[(size_t)(k + 1) * (N_ / 4)];
            qB1 = qb[(size_t)(k + 1) * (N_ / 4) + 1];
        }
        const unsigned long long q0 = pk2(qA0.x, qA0.x);
        const unsigned long long q1 = pk2(qA0.y, qA0.y);
        const unsigned long long q2 = pk2(qA0.z, qA0.z);
        const unsigned long long q3 = pk2(qA0.w, qA0.w);
        const unsigned long long q4 = pk2(qA1.x, qA1.x);
        const unsigned long long q5 = pk2(qA1.y, qA1.y);
        const unsigned long long q6 = pk2(qA1.z, qA1.z);
        const unsigned long long q7 = pk2(qA1.w, qA1.w);
        const ulonglong2* vr = &svals[(size_t)k * 8 + half * JM];
#pragma unroll
        for (int j = 0; j < JM; j++) {
            const ulonglong2 v = vr[j];
            acc[0][2 * j + 0] = ffma2(q0, v.x, acc[0][2 * j + 0]);
            acc[0][2 * j + 1] = ffma2(q0, v.y, acc[0][2 * j + 1]);
            acc[1][2 * j + 0] = ffma2(q1, v.x, acc[1][2 * j + 0]);
            acc[1][2 * j + 1] = ffma2(q1, v.y, acc[1][2 * j + 1]);
            acc[2][2 * j + 0] = ffma2(q2, v.x, acc[2][2 * j + 0]);
            acc[2][2 * j + 1] = ffma2(q2, v.y, acc[2][2 * j + 1]);
            acc[3][2 * j + 0] = ffma2(q3, v.x, acc[3][2 * j + 0]);
            acc[3][2 * j + 1] = ffma2(q3, v.y, acc[3][2 * j + 1]);
            acc[4][2 * j + 0] = ffma2(q4, v.x, acc[4][2 * j + 0]);
            acc[4][2 * j + 1] = ffma2(q4, v.y, acc[4][2 * j + 1]);
            acc[5][2 * j + 0] = ffma2(q5, v.x, acc[5][2 * j + 0]);
            acc[5][2 * j + 1] = ffma2(q5, v.y, acc[5][2 * j + 1]);
            acc[6][2 * j + 0] = ffma2(q6, v.x, acc[6][2 * j + 0]);
            acc[6][2 * j + 1] = ffma2(q6, v.y, acc[6][2 * j + 1]);
            acc[7][2 * j + 0] = ffma2(q7, v.x, acc[7][2 * j + 0]);
            acc[7][2 * j + 1] = ffma2(q7, v.y, acc[7][2 * j + 1]);
        }
        qA0 = qB0;
        qA1 = qB1;
    }

    // ---- zero-fill coefficient rows ----
#pragma unroll
    for (int px = 0; px < 8; px++) {
        float4* z = reinterpret_cast<float4*>(ocb + px * T_ + half * 16);
#pragma unroll
        for (int j = 0; j < 4; j++) z[j] = make_float4(0.f, 0.f, 0.f, 0.f);
    }

    // ---- phase 2: softmax per pixel ----
#pragma unroll
    for (int px = 0; px < 8; px++) {
        const unsigned long long* snp =
            reinterpret_cast<const unsigned long long*>(&scs[cb]);
        float Sv[2 * NJ];
#pragma unroll
        for (int j = 0; j < NJ; j++) {
            const float2 f = unpk2(add2(acc[px][j], snp[j]));
            Sv[2 * j + 0] = f.x;
            Sv[2 * j + 1] = f.y;
        }
        float m = -CUDART_INF_F;
#pragma unroll
        for (int i = 0; i < 2 * NJ; i++) m = fmaxf(m, Sv[i]);
        m = fmaxf(m, __shfl_xor_sync(0xffffffffu, m, 1));
        float sum = 0.f;
#pragma unroll
        for (int i = 0; i < 2 * NJ; i++) {
            Sv[i] = __expf(Sv[i] - m);
            sum += Sv[i];
        }
        sum += __shfl_xor_sync(0xffffffffu, sum, 1);
        const float inv = 1.0f / sum;
#pragma unroll
        for (int i = 0; i < 2 * NJ; i++) Sv[i] *= inv;
#pragma unroll
        for (int j = 0; j < NJ; j++)
            acc[px][j] = pk2(Sv[2 * j], Sv[2 * j + 1]);
    }

    // ---- scatter coefficients ----
    __syncwarp();
#pragma unroll
    for (int px = 0; px < 8; px++) {
        float* oc = ocb + px * T_;
#pragma unroll
        for (int j = 0; j < NJ; j++) {
            const float2 f = unpk2(acc[px][j]);
            oc[stl[cb + 2 * j + 0]] = f.x;
            oc[stl[cb + 2 * j + 1]] = f.y;
        }
    }

    // ---- phase 3: even lane stores px0-3, odd px4-7 (float4) ----
    for (int k = 0; k < DH_; k += 2) {
        unsigned long long mine[2][2], sent[2][2];
#pragma unroll
        for (int kk = 0; kk < 2; kk++) {
            const ulonglong2* vr = &svals[(size_t)(k + kk) * 8 + half * JM];
            unsigned long long a[8];
#pragma unroll
            for (int px = 0; px < 8; px++) a[px] = 0ULL;
#pragma unroll
            for (int j = 0; j < JM; j++) {
                const ulonglong2 v = vr[j];
#pragma unroll
                for (int px = 0; px < 8; px++) {
                    a[px] = ffma2(v.x, acc[px][2 * j + 0], a[px]);
                    a[px] = ffma2(v.y, acc[px][2 * j + 1], a[px]);
                }
            }
            float2 f[8];
#pragma unroll
            for (int px = 0; px < 8; px++) f[px] = unpk2(a[px]);
            const unsigned long long p01 = pk2(f[0].x + f[0].y, f[1].x + f[1].y);
            const unsigned long long p23 = pk2(f[2].x + f[2].y, f[3].x + f[3].y);
            const unsigned long long p45 = pk2(f[4].x + f[4].y, f[5].x + f[5].y);
            const unsigned long long p67 = pk2(f[6].x + f[6].y, f[7].x + f[7].y);
            if (half == 0) {
                mine[kk][0] = p01; mine[kk][1] = p23;
                sent[kk][0] = p45; sent[kk][1] = p67;
            } else {
                mine[kk][0] = p45; mine[kk][1] = p67;
                sent[kk][0] = p01; sent[kk][1] = p23;
            }
        }
        unsigned long long got[2][2];
#pragma unroll
        for (int kk = 0; kk < 2; kk++) {
            got[kk][0] = __shfl_xor_sync(0xffffffffu, sent[kk][0], 1);
            got[kk][1] = __shfl_xor_sync(0xffffffffu, sent[kk][1], 1);
        }
#pragma unroll
        for (int kk = 0; kk < 2; kk++) {
            const float2 rA = unpk2(add2(mine[kk][0], got[kk][0]));
            const float2 rB = unpk2(add2(mine[kk][1], got[kk][1]));
            float4 r;
            r.x = rA.x; r.y = rA.y; r.z = rB.x; r.w = rB.y;
            *reinterpret_cast<float4*>(oa + (size_t)(k + kk) * N_) = r;
        }
    }
}

// ---------------- kernel 2: compaction + gather + dispatch ----------------
// block = 256 (8 warps); pair covers 8 pixels; warp 128 px; CTA 1024 px.
// grid = (N/1024, B).
__global__ __launch_bounds__(256, 2)
void attn_kernel(const float* __restrict__ img,
                 const int* __restrict__ mask,
                 float* __restrict__ out_attn,
                 float* __restrict__ out_coef) {
    __shared__ __align__(16) float svf[DH_ * T_];
    __shared__ __align__(8) float scs[T_];
    __shared__ int stl[T_];
    __shared__ int sjm;

    const int b = blockIdx.y;
    const int tid = threadIdx.x;
    const int lane = tid & 31;
    const int warp = tid >> 5;
    const int half = lane & 1;
    const int pair = lane >> 1;
    const int n0 = blockIdx.x * 1024 + warp * 128 + pair * 8;

    // in-CTA mask compaction (warp 0)
    if (tid < 32) {
        const int m = mask[b * T_ + tid];
        const unsigned bal = __ballot_sync(0xffffffffu, m == 0);
        const int Tc = __popc(bal);
        int Tcp = (Tc + 7) & ~7;
        if (Tcp < 8) Tcp = 8;
        if (m == 0) {
            const int pos = __popc(bal & ((1u << tid) - 1u));
            stl[pos] = tid;
        }
        const unsigned mb = ~bal;
        const int firstMasked = mb ? (__ffs(mb) - 1) : 0;
        if (tid >= Tc) stl[tid] = firstMasked;
        scs[tid] = (tid < Tc) ? 0.0f : -CUDART_INF_F;
        if (tid == 0) sjm = Tcp >> 3;
    }
    __syncthreads();

    // gather compact values rows
    const float* gvb = g_values + (size_t)b * DH_ * T_;
#pragma unroll
    for (int i = 0; i < 16; i++) {
        const int f = tid + 256 * i;
        svf[f] = gvb[(f & ~31) + stl[f & 31]];
    }
    __syncthreads();

    const int jm = sjm;
    const ulonglong2* sv = reinterpret_cast<const ulonglong2*>(svf);
    const float* imb = img + (size_t)b * DH_ * N_;

    if (jm == 2) {
        attn_core8<2>(sv, scs, stl,
                      reinterpret_cast<const float4*>(imb + n0),
                      out_coef + ((size_t)b * N_ + n0) * T_,
                      out_attn + (size_t)b * DH_ * N_ + n0 + 4 * half, half);
    } else if (jm == 3) {
#pragma unroll 1
        for (int g = 0; g < 2; g++) {
            const int ng = n0 + 4 * g;
            attn_core4<3>(sv, scs, stl,
                          reinterpret_cast<const float4*>(imb + ng),
                          out_coef + ((size_t)b * N_ + ng) * T_,
                          out_attn + (size_t)b * DH_ * N_ + ng + 2 * half,
                          half);
        }
    } else if (jm == 1) {
        attn_core8<1>(sv, scs, stl,
                      reinterpret_cast<const float4*>(imb + n0),
                      out_coef + ((size_t)b * N_ + n0) * T_,
                      out_attn + (size_t)b * DH_ * N_ + n0 + 4 * half, half);
    } else {
#pragma unroll 1
        for (int g = 0; g < 2; g++) {
            const int ng = n0 + 4 * g;
            attn_core4<4>(sv, scs, stl,
                          reinterpret_cast<const float4*>(imb + ng),
                          out_coef + ((size_t)b * N_ + ng) * T_,
                          out_attn + (size_t)b * DH_ * N_ + ng + 2 * half,
                          half);
        }
    }
}

extern "C" void kernel_launch(void* const* d_in, const int* in_sizes, int n_in,
                              void* d_out, int out_size) {
    const float* wf   = (const float*)d_in[0];
    const float* img  = (const float*)d_in[1];
    const int*   msk  = (const int*)d_in[2];
    const float* Wm   = (const float*)d_in[3];
    const float* bias = (const float*)d_in[4];

    float* out_attn = (float*)d_out;
    float* out_coef = (float*)d_out + (size_t)B_ * DH_ * N_;

    dim3 vgrid(4, B_);
    values_kernel<<<vgrid, 256>>>(wf, Wm, bias);

    dim3 grid(N_ / 1024, B_);
    attn_kernel<<<grid, 256>>>(img, msk, out_attn, out_coef);
}

// round 14
// speedup vs baseline: 1.2551x; 1.2551x over previous
#include <cuda_runtime.h>
#include <math_constants.h>
#include <cstdint>

// Shapes (fixed):
//   word_features  [B, D, T]   = [32, 256, 32]   fp32   d_in[0]
//   image_features [B, Dh,H,W] = [32, 128,128,128] fp32 d_in[1]
//   words_mask     [B, T]      = [32, 32]        int32  d_in[2]
//   W              [Dh, D]     = [128, 256]      fp32   d_in[3]
//   b              [Dh]        = [128]           fp32   d_in[4]
// Outputs: attn [B,Dh,N] at 0, attn_coefficients [B,N,T] at B*Dh*N.
//
// R11 structure (best: 186.5us) + deeper q prefetch (8-deep) in the JM<=2
// branches, where the register allocator has slack (kernel allocation is set
// by the JM4 branch). Masked t columns are compacted per batch in-CTA.

#define B_   32
#define D_   256
#define T_   32
#define DH_  128
#define N_   16384

__device__ float g_values[B_ * DH_ * T_];

// ---------------- packed f32x2 helpers ----------------
__device__ __forceinline__ unsigned long long pk2(float lo, float hi) {
    unsigned long long r;
    asm("mov.b64 %0, {%1, %2};" : "=l"(r) : "f"(lo), "f"(hi));
    return r;
}
__device__ __forceinline__ float2 unpk2(unsigned long long v) {
    float2 f;
    asm("mov.b64 {%0, %1}, %2;" : "=f"(f.x), "=f"(f.y) : "l"(v));
    return f;
}
__device__ __forceinline__ unsigned long long ffma2(unsigned long long a,
                                                    unsigned long long b,
                                                    unsigned long long c) {
    unsigned long long d;
    asm("fma.rn.f32x2 %0, %1, %2, %3;" : "=l"(d) : "l"(a), "l"(b), "l"(c));
    return d;
}
__device__ __forceinline__ unsigned long long add2(unsigned long long a,
                                                   unsigned long long b) {
    unsigned long long d;
    asm("add.rn.f32x2 %0, %1, %2;" : "=l"(d) : "l"(a), "l"(b));
    return d;
}

// ---------------- kernel 1: values = W * wf + b ----------------
#define SW_PAD 264
__global__ __launch_bounds__(256)
void values_kernel(const float* __restrict__ wf,
                   const float* __restrict__ Wm,
                   const float* __restrict__ bias) {
    __shared__ float swf[D_ * T_];
    __shared__ float sW[32 * SW_PAD];
    const int c = blockIdx.x;
    const int b = blockIdx.y;
    const int tid = threadIdx.x;

    {
        const float4* src =
            reinterpret_cast<const float4*>(wf + (size_t)b * D_ * T_);
        float4* dst = reinterpret_cast<float4*>(swf);
#pragma unroll
        for (int i = 0; i < 8; i++) dst[tid + 256 * i] = src[tid + 256 * i];

        const float4* wsrc =
            reinterpret_cast<const float4*>(Wm + (size_t)c * 32 * D_);
#pragma unroll
        for (int i = 0; i < 8; i++) {
            const int idx = tid + 256 * i;
            const int kl = idx >> 6;
            const int dc = idx & 63;
            float4 v = wsrc[idx];
            *reinterpret_cast<float4*>(&sW[kl * SW_PAD + dc * 4]) = v;
        }
    }
    __syncthreads();

    const int k_l = tid >> 3;
    const int tq = tid & 7;
    const int k = c * 32 + k_l;

    const float bk = bias[k];
    unsigned long long acc0 = pk2(bk, bk);
    unsigned long long acc1 = pk2(bk, bk);

#pragma unroll 4
    for (int d = 0; d < D_; d++) {
        const float w = sW[k_l * SW_PAD + d];
        const unsigned long long wp = pk2(w, w);
        const ulonglong2 v =
            *reinterpret_cast<const ulonglong2*>(&swf[d * T_ + tq * 4]);
        acc0 = ffma2(wp, v.x, acc0);
        acc1 = ffma2(wp, v.y, acc1);
    }

    ulonglong2 o;
    o.x = acc0;
    o.y = acc1;
    *reinterpret_cast<ulonglong2*>(
        g_values + ((size_t)b * DH_ + k) * T_ + tq * 4) = o;
}

// ---------------- templated attention core (JM = Tcp/8, 1..4) ----------------
// Lane pair (2p,2p+1) shares 4 pixels; even lane owns compact cols
// [0, 4*JM), odd lane [4*JM, 8*JM). Phase 3 combines halves via one 64-bit
// shuffle per k (batched by 4). q prefetch depth: 8 for JM<=2 (register
// slack), 4 for JM>=3 (R11-identical).
template <int JM>
__device__ __forceinline__ void attn_core(
    const ulonglong2* __restrict__ svals,
    const float* __restrict__ scs,
    const int* __restrict__ stl,
    const float4* __restrict__ qb,
    float* __restrict__ ocb,
    float* __restrict__ oa,
    const int half) {
    constexpr int NJ = 2 * JM;
    constexpr int PF = (JM <= 2) ? 8 : 4;  // q prefetch depth
    const int cb = half * 4 * JM;

    unsigned long long acc[4][NJ];
#pragma unroll
    for (int px = 0; px < 4; px++)
#pragma unroll
        for (int j = 0; j < NJ; j++) acc[px][j] = 0ULL;

    // ---- phase 1: S_compact = sum_k q * vals_compact ----
    float4 qv[PF];
#pragma unroll
    for (int kk = 0; kk < PF; kk++) qv[kk] = qb[(size_t)kk * (N_ / 4)];

    for (int k = 0; k < DH_; k += PF) {
        float4 qn[PF];
        if (k + PF < DH_) {
#pragma unroll
            for (int kk = 0; kk < PF; kk++)
                qn[kk] = qb[(size_t)(k + PF + kk) * (N_ / 4)];
        }
#pragma unroll
        for (int kk = 0; kk < PF; kk++) {
            const unsigned long long q0 = pk2(qv[kk].x, qv[kk].x);
            const unsigned long long q1 = pk2(qv[kk].y, qv[kk].y);
            const unsigned long long q2 = pk2(qv[kk].z, qv[kk].z);
            const unsigned long long q3 = pk2(qv[kk].w, qv[kk].w);
            const ulonglong2* vr = &svals[(size_t)(k + kk) * 8 + half * JM];
#pragma unroll
            for (int j = 0; j < JM; j++) {
                const ulonglong2 v = vr[j];
                acc[0][2 * j + 0] = ffma2(q0, v.x, acc[0][2 * j + 0]);
                acc[0][2 * j + 1] = ffma2(q0, v.y, acc[0][2 * j + 1]);
                acc[1][2 * j + 0] = ffma2(q1, v.x, acc[1][2 * j + 0]);
                acc[1][2 * j + 1] = ffma2(q1, v.y, acc[1][2 * j + 1]);
                acc[2][2 * j + 0] = ffma2(q2, v.x, acc[2][2 * j + 0]);
                acc[2][2 * j + 1] = ffma2(q2, v.y, acc[2][2 * j + 1]);
                acc[3][2 * j + 0] = ffma2(q3, v.x, acc[3][2 * j + 0]);
                acc[3][2 * j + 1] = ffma2(q3, v.y, acc[3][2 * j + 1]);
            }
        }
#pragma unroll
        for (int kk = 0; kk < PF; kk++) qv[kk] = qn[kk];
    }

    // ---- zero-fill coefficient rows (pair covers full 32-col row) ----
#pragma unroll
    for (int px = 0; px < 4; px++) {
        float4* z = reinterpret_cast<float4*>(ocb + px * T_ + half * 16);
#pragma unroll
        for (int j = 0; j < 4; j++) z[j] = make_float4(0.f, 0.f, 0.f, 0.f);
    }

    // ---- phase 2: softmax over compact cols (pads -> -inf -> 0) ----
#pragma unroll
    for (int px = 0; px < 4; px++) {
        const unsigned long long* snp =
            reinterpret_cast<const unsigned long long*>(&scs[cb]);
        float Sv[2 * NJ];
#pragma unroll
        for (int j = 0; j < NJ; j++) {
            const float2 f = unpk2(add2(acc[px][j], snp[j]));
            Sv[2 * j + 0] = f.x;
            Sv[2 * j + 1] = f.y;
        }
        float m = -CUDART_INF_F;
#pragma unroll
        for (int i = 0; i < 2 * NJ; i++) m = fmaxf(m, Sv[i]);
        m = fmaxf(m, __shfl_xor_sync(0xffffffffu, m, 1));
        float sum = 0.f;
#pragma unroll
        for (int i = 0; i < 2 * NJ; i++) {
            Sv[i] = __expf(Sv[i] - m);
            sum += Sv[i];
        }
        sum += __shfl_xor_sync(0xffffffffu, sum, 1);
        const float inv = 1.0f / sum;
#pragma unroll
        for (int i = 0; i < 2 * NJ; i++) Sv[i] *= inv;
#pragma unroll
        for (int j = 0; j < NJ; j++)
            acc[px][j] = pk2(Sv[2 * j], Sv[2 * j + 1]);
    }

    // ---- scatter coefficients (pads write exact 0 to a masked col) ----
    __syncwarp();  // order partner's zero-fill before scatter
#pragma unroll
    for (int px = 0; px < 4; px++) {
        float* oc = ocb + px * T_;
#pragma unroll
        for (int j = 0; j < NJ; j++) {
            const float2 f = unpk2(acc[px][j]);
            oc[stl[cb + 2 * j + 0]] = f.x;
            oc[stl[cb + 2 * j + 1]] = f.y;
        }
    }

    // ---- phase 3: attn[k] = sum_compact vals * p, half-t partials ----
    for (int k = 0; k < DH_; k += 4) {
        unsigned long long mine[4], sent[4];
#pragma unroll
        for (int kk = 0; kk < 4; kk++) {
            const ulonglong2* vr = &svals[(size_t)(k + kk) * 8 + half * JM];
            unsigned long long a0 = 0ULL, a1 = 0ULL, a2 = 0ULL, a3 = 0ULL;
#pragma unroll
            for (int j = 0; j < JM; j++) {
                const ulonglong2 v = vr[j];
                a0 = ffma2(v.x, acc[0][2 * j + 0], a0);
                a0 = ffma2(v.y, acc[0][2 * j + 1], a0);
                a1 = ffma2(v.x, acc[1][2 * j + 0], a1);
                a1 = ffma2(v.y, acc[1][2 * j + 1], a1);
                a2 = ffma2(v.x, acc[2][2 * j + 0], a2);
                a2 = ffma2(v.y, acc[2][2 * j + 1], a2);
                a3 = ffma2(v.x, acc[3][2 * j + 0], a3);
                a3 = ffma2(v.y, acc[3][2 * j + 1], a3);
            }
            const float2 f0 = unpk2(a0), f1 = unpk2(a1);
            const float2 f2 = unpk2(a2), f3 = unpk2(a3);
            const unsigned long long p01 = pk2(f0.x + f0.y, f1.x + f1.y);
            const unsigned long long p23 = pk2(f2.x + f2.y, f3.x + f3.y);
            sent[kk] = half ? p01 : p23;
            mine[kk] = half ? p23 : p01;
        }
        unsigned long long got[4];
#pragma unroll
        for (int kk = 0; kk < 4; kk++)
            got[kk] = __shfl_xor_sync(0xffffffffu, sent[kk], 1);
#pragma unroll
        for (int kk = 0; kk < 4; kk++) {
            const float2 r = unpk2(add2(mine[kk], got[kk]));
            *reinterpret_cast<float2*>(oa + (size_t)(k + kk) * N_) =
                make_float2(r.x, r.y);
        }
    }
}

// ---------------- kernel 2: in-CTA compaction + gather + dispatch ----------------
__global__ __launch_bounds__(256, 2)
void attn_kernel(const float* __restrict__ img,
                 const int* __restrict__ mask,
                 float* __restrict__ out_attn,
                 float* __restrict__ out_coef) {
    __shared__ __align__(16) float svf[DH_ * T_];
    __shared__ __align__(8) float scs[T_];
    __shared__ int stl[T_];
    __shared__ int sjm;

    const int b = blockIdx.y;
    const int tid = threadIdx.x;
    const int lane = tid & 31;
    const int warp = tid >> 5;
    const int half = lane & 1;
    const int pair = lane >> 1;
    const int n0 = blockIdx.x * 512 + warp * 64 + pair * 4;

    // in-CTA mask compaction (warp 0)
    if (tid < 32) {
        const int m = mask[b * T_ + tid];
        const unsigned bal = __ballot_sync(0xffffffffu, m == 0);
        const int Tc = __popc(bal);
        int Tcp = (Tc + 7) & ~7;
        if (Tcp < 8) Tcp = 8;
        if (m == 0) {
            const int pos = __popc(bal & ((1u << tid) - 1u));
            stl[pos] = tid;
        }
        const unsigned mb = ~bal;
        const int firstMasked = mb ? (__ffs(mb) - 1) : 0;
        if (tid >= Tc) stl[tid] = firstMasked;
        scs[tid] = (tid < Tc) ? 0.0f : -CUDART_INF_F;
        if (tid == 0) sjm = Tcp >> 3;
    }
    __syncthreads();

    // gather compact values rows (permutation within 128B lines -> coalesced)
    const float* gvb = g_values + (size_t)b * DH_ * T_;
#pragma unroll
    for (int i = 0; i < 16; i++) {
        const int f = tid + 256 * i;
        svf[f] = gvb[(f & ~31) + stl[f & 31]];
    }
    __syncthreads();

    const int jm = sjm;

    const float4* qb =
        reinterpret_cast<const float4*>(img + (size_t)b * DH_ * N_ + n0);
    float* ocb = out_coef + ((size_t)b * N_ + n0) * T_;
    float* oa = out_attn + (size_t)b * DH_ * N_ + n0 + 2 * half;
    const ulonglong2* sv = reinterpret_cast<const ulonglong2*>(svf);

    if (jm == 2)
        attn_core<2>(sv, scs, stl, qb, ocb, oa, half);
    else if (jm == 3)
        attn_core<3>(sv, scs, stl, qb, ocb, oa, half);
    else if (jm == 4)
        attn_core<4>(sv, scs, stl, qb, ocb, oa, half);
    else
        attn_core<1>(sv, scs, stl, qb, ocb, oa, half);
}

extern "C" void kernel_launch(void* const* d_in, const int* in_sizes, int n_in,
                              void* d_out, int out_size) {
    const float* wf   = (const float*)d_in[0];
    const float* img  = (const float*)d_in[1];
    const int*   msk  = (const int*)d_in[2];
    const float* Wm   = (const float*)d_in[3];
    const float* bias = (const float*)d_in[4];

    float* out_attn = (float*)d_out;
    float* out_coef = (float*)d_out + (size_t)B_ * DH_ * N_;

    dim3 vgrid(4, B_);
    values_kernel<<<vgrid, 256>>>(wf, Wm, bias);

    dim3 grid(N_ / 512, B_);
    attn_kernel<<<grid, 256>>>(img, msk, out_attn, out_coef);
}

// round 15
// speedup vs baseline: 1.4929x; 1.1895x over previous
#include <cuda_runtime.h>
#include <math_constants.h>
#include <cstdint>

// Shapes (fixed):
//   word_features  [B, D, T]   = [32, 256, 32]   fp32   d_in[0]
//   image_features [B, Dh,H,W] = [32, 128,128,128] fp32 d_in[1]
//   words_mask     [B, T]      = [32, 32]        int32  d_in[2]
//   W              [Dh, D]     = [128, 256]      fp32   d_in[3]
//   b              [Dh]        = [128]           fp32   d_in[4]
// Outputs: attn [B,Dh,N] at 0, attn_coefficients [B,N,T] at B*Dh*N.
//
// R14 core (best: 184.8us) + smem-staged coefficient writes: scatter compact
// softmax values into a padded per-warp smem scratch, then copy out with
// coalesced STG.128 (kills the 16-line write-wavefront amplification of the
// direct gmem scatter).

#define B_   32
#define D_   256
#define T_   32
#define DH_  128
#define N_   16384

__device__ float g_values[B_ * DH_ * T_];

// ---------------- packed f32x2 helpers ----------------
__device__ __forceinline__ unsigned long long pk2(float lo, float hi) {
    unsigned long long r;
    asm("mov.b64 %0, {%1, %2};" : "=l"(r) : "f"(lo), "f"(hi));
    return r;
}
__device__ __forceinline__ float2 unpk2(unsigned long long v) {
    float2 f;
    asm("mov.b64 {%0, %1}, %2;" : "=f"(f.x), "=f"(f.y) : "l"(v));
    return f;
}
__device__ __forceinline__ unsigned long long ffma2(unsigned long long a,
                                                    unsigned long long b,
                                                    unsigned long long c) {
    unsigned long long d;
    asm("fma.rn.f32x2 %0, %1, %2, %3;" : "=l"(d) : "l"(a), "l"(b), "l"(c));
    return d;
}
__device__ __forceinline__ unsigned long long add2(unsigned long long a,
                                                   unsigned long long b) {
    unsigned long long d;
    asm("add.rn.f32x2 %0, %1, %2;" : "=l"(d) : "l"(a), "l"(b));
    return d;
}

// ---------------- kernel 1: values = W * wf + b ----------------
#define SW_PAD 264
__global__ __launch_bounds__(256)
void values_kernel(const float* __restrict__ wf,
                   const float* __restrict__ Wm,
                   const float* __restrict__ bias) {
    __shared__ float swf[D_ * T_];
    __shared__ float sW[32 * SW_PAD];
    const int c = blockIdx.x;
    const int b = blockIdx.y;
    const int tid = threadIdx.x;

    {
        const float4* src =
            reinterpret_cast<const float4*>(wf + (size_t)b * D_ * T_);
        float4* dst = reinterpret_cast<float4*>(swf);
#pragma unroll
        for (int i = 0; i < 8; i++) dst[tid + 256 * i] = src[tid + 256 * i];

        const float4* wsrc =
            reinterpret_cast<const float4*>(Wm + (size_t)c * 32 * D_);
#pragma unroll
        for (int i = 0; i < 8; i++) {
            const int idx = tid + 256 * i;
            const int kl = idx >> 6;
            const int dc = idx & 63;
            float4 v = wsrc[idx];
            *reinterpret_cast<float4*>(&sW[kl * SW_PAD + dc * 4]) = v;
        }
    }
    __syncthreads();

    const int k_l = tid >> 3;
    const int tq = tid & 7;
    const int k = c * 32 + k_l;

    const float bk = bias[k];
    unsigned long long acc0 = pk2(bk, bk);
    unsigned long long acc1 = pk2(bk, bk);

#pragma unroll 4
    for (int d = 0; d < D_; d++) {
        const float w = sW[k_l * SW_PAD + d];
        const unsigned long long wp = pk2(w, w);
        const ulonglong2 v =
            *reinterpret_cast<const ulonglong2*>(&swf[d * T_ + tq * 4]);
        acc0 = ffma2(wp, v.x, acc0);
        acc1 = ffma2(wp, v.y, acc1);
    }

    ulonglong2 o;
    o.x = acc0;
    o.y = acc1;
    *reinterpret_cast<ulonglong2*>(
        g_values + ((size_t)b * DH_ + k) * T_ + tq * 4) = o;
}

// ---------------- templated attention core (JM = Tcp/8, 1..4) ----------------
// Lane pair (2p,2p+1) shares 4 pixels; even lane owns compact cols
// [0, 4*JM), odd lane [4*JM, 8*JM). Coefficients are staged in a padded
// per-warp smem scratch (wb: 64 rows x 33 floats) then copied out coalesced.
template <int JM>
__device__ __forceinline__ void attn_core(
    const ulonglong2* __restrict__ svals,
    const float* __restrict__ scs,
    const int* __restrict__ stl,
    const float4* __restrict__ qb,
    float* __restrict__ wb,    // per-warp coef scratch (64*33 floats)
    float* __restrict__ ogc,   // out_coef warp base (64 rows x 32 floats)
    float* __restrict__ oa,    // out_attn + b*Dh*N + n0 + 2*half
    const int half, const int pair, const int lane) {
    constexpr int NJ = 2 * JM;
    constexpr int PF = (JM <= 2) ? 8 : 4;  // q prefetch depth
    const int cb = half * 4 * JM;

    // zero the warp's coef scratch (2112 floats = 528 float4)
    {
        const float4 z4 = make_float4(0.f, 0.f, 0.f, 0.f);
        float4* wz = reinterpret_cast<float4*>(wb);
        for (int i = lane; i < 528; i += 32) wz[i] = z4;
    }

    unsigned long long acc[4][NJ];
#pragma unroll
    for (int px = 0; px < 4; px++)
#pragma unroll
        for (int j = 0; j < NJ; j++) acc[px][j] = 0ULL;

    // ---- phase 1: S_compact = sum_k q * vals_compact ----
    float4 qv[PF];
#pragma unroll
    for (int kk = 0; kk < PF; kk++) qv[kk] = qb[(size_t)kk * (N_ / 4)];

    for (int k = 0; k < DH_; k += PF) {
        float4 qn[PF];
        if (k + PF < DH_) {
#pragma unroll
            for (int kk = 0; kk < PF; kk++)
                qn[kk] = qb[(size_t)(k + PF + kk) * (N_ / 4)];
        }
#pragma unroll
        for (int kk = 0; kk < PF; kk++) {
            const unsigned long long q0 = pk2(qv[kk].x, qv[kk].x);
            const unsigned long long q1 = pk2(qv[kk].y, qv[kk].y);
            const unsigned long long q2 = pk2(qv[kk].z, qv[kk].z);
            const unsigned long long q3 = pk2(qv[kk].w, qv[kk].w);
            const ulonglong2* vr = &svals[(size_t)(k + kk) * 8 + half * JM];
#pragma unroll
            for (int j = 0; j < JM; j++) {
                const ulonglong2 v = vr[j];
                acc[0][2 * j + 0] = ffma2(q0, v.x, acc[0][2 * j + 0]);
                acc[0][2 * j + 1] = ffma2(q0, v.y, acc[0][2 * j + 1]);
                acc[1][2 * j + 0] = ffma2(q1, v.x, acc[1][2 * j + 0]);
                acc[1][2 * j + 1] = ffma2(q1, v.y, acc[1][2 * j + 1]);
                acc[2][2 * j + 0] = ffma2(q2, v.x, acc[2][2 * j + 0]);
                acc[2][2 * j + 1] = ffma2(q2, v.y, acc[2][2 * j + 1]);
                acc[3][2 * j + 0] = ffma2(q3, v.x, acc[3][2 * j + 0]);
                acc[3][2 * j + 1] = ffma2(q3, v.y, acc[3][2 * j + 1]);
            }
        }
#pragma unroll
        for (int kk = 0; kk < PF; kk++) qv[kk] = qn[kk];
    }

    // ---- phase 2: softmax over compact cols (pads -> -inf -> 0) ----
#pragma unroll
    for (int px = 0; px < 4; px++) {
        const unsigned long long* snp =
            reinterpret_cast<const unsigned long long*>(&scs[cb]);
        float Sv[2 * NJ];
#pragma unroll
        for (int j = 0; j < NJ; j++) {
            const float2 f = unpk2(add2(acc[px][j], snp[j]));
            Sv[2 * j + 0] = f.x;
            Sv[2 * j + 1] = f.y;
        }
        float m = -CUDART_INF_F;
#pragma unroll
        for (int i = 0; i < 2 * NJ; i++) m = fmaxf(m, Sv[i]);
        m = fmaxf(m, __shfl_xor_sync(0xffffffffu, m, 1));
        float sum = 0.f;
#pragma unroll
        for (int i = 0; i < 2 * NJ; i++) {
            Sv[i] = __expf(Sv[i] - m);
            sum += Sv[i];
        }
        sum += __shfl_xor_sync(0xffffffffu, sum, 1);
        const float inv = 1.0f / sum;
#pragma unroll
        for (int i = 0; i < 2 * NJ; i++) Sv[i] *= inv;
#pragma unroll
        for (int j = 0; j < NJ; j++)
            acc[px][j] = pk2(Sv[2 * j], Sv[2 * j + 1]);
    }

    // ---- scatter coefficients into smem scratch (pads write exact 0) ----
    __syncwarp();  // order scratch zeroing before scatter
#pragma unroll
    for (int px = 0; px < 4; px++) {
        float* r = wb + (pair * 4 + px) * 33;
#pragma unroll
        for (int j = 0; j < NJ; j++) {
            const float2 f = unpk2(acc[px][j]);
            r[stl[cb + 2 * j + 0]] = f.x;
            r[stl[cb + 2 * j + 1]] = f.y;
        }
    }
    __syncwarp();  // scatter visible to all lanes before copy-out

    // ---- coalesced copy-out: 64 rows x 32 floats -> contiguous gmem ----
    {
        float4* og4 = reinterpret_cast<float4*>(ogc);
#pragma unroll
        for (int i = 0; i < 16; i++) {
            const int i16 = i * 32 + lane;
            const int row = i16 >> 3;
            const int c4 = (i16 & 7) * 4;
            const float* rp = wb + row * 33 + c4;
            float4 v;
            v.x = rp[0];
            v.y = rp[1];
            v.z = rp[2];
            v.w = rp[3];
            og4[i16] = v;
        }
    }

    // ---- phase 3: attn[k] = sum_compact vals * p, half-t partials ----
    for (int k = 0; k < DH_; k += 4) {
        unsigned long long mine[4], sent[4];
#pragma unroll
        for (int kk = 0; kk < 4; kk++) {
            const ulonglong2* vr = &svals[(size_t)(k + kk) * 8 + half * JM];
            unsigned long long a0 = 0ULL, a1 = 0ULL, a2 = 0ULL, a3 = 0ULL;
#pragma unroll
            for (int j = 0; j < JM; j++) {
                const ulonglong2 v = vr[j];
                a0 = ffma2(v.x, acc[0][2 * j + 0], a0);
                a0 = ffma2(v.y, acc[0][2 * j + 1], a0);
                a1 = ffma2(v.x, acc[1][2 * j + 0], a1);
                a1 = ffma2(v.y, acc[1][2 * j + 1], a1);
                a2 = ffma2(v.x, acc[2][2 * j + 0], a2);
                a2 = ffma2(v.y, acc[2][2 * j + 1], a2);
                a3 = ffma2(v.x, acc[3][2 * j + 0], a3);
                a3 = ffma2(v.y, acc[3][2 * j + 1], a3);
            }
            const float2 f0 = unpk2(a0), f1 = unpk2(a1);
            const float2 f2 = unpk2(a2), f3 = unpk2(a3);
            const unsigned long long p01 = pk2(f0.x + f0.y, f1.x + f1.y);
            const unsigned long long p23 = pk2(f2.x + f2.y, f3.x + f3.y);
            sent[kk] = half ? p01 : p23;
            mine[kk] = half ? p23 : p01;
        }
        unsigned long long got[4];
#pragma unroll
        for (int kk = 0; kk < 4; kk++)
            got[kk] = __shfl_xor_sync(0xffffffffu, sent[kk], 1);
#pragma unroll
        for (int kk = 0; kk < 4; kk++) {
            const float2 r = unpk2(add2(mine[kk], got[kk]));
            *reinterpret_cast<float2*>(oa + (size_t)(k + kk) * N_) =
                make_float2(r.x, r.y);
        }
    }
}

// ---------------- kernel 2: in-CTA compaction + gather + dispatch ----------------
__global__ __launch_bounds__(256, 2)
void attn_kernel(const float* __restrict__ img,
                 const int* __restrict__ mask,
                 float* __restrict__ out_attn,
                 float* __restrict__ out_coef) {
    __shared__ __align__(16) float svf[DH_ * T_];
    __shared__ __align__(8) float scs[T_];
    __shared__ int stl[T_];
    __shared__ int sjm;
    __shared__ __align__(16) float scoef[8 * 64 * 33];  // 8 warps x 8448B

    const int b = blockIdx.y;
    const int tid = threadIdx.x;
    const int lane = tid & 31;
    const int warp = tid >> 5;
    const int half = lane & 1;
    const int pair = lane >> 1;
    const int n0 = blockIdx.x * 512 + warp * 64 + pair * 4;

    // in-CTA mask compaction (warp 0)
    if (tid < 32) {
        const int m = mask[b * T_ + tid];
        const unsigned bal = __ballot_sync(0xffffffffu, m == 0);
        const int Tc = __popc(bal);
        int Tcp = (Tc + 7) & ~7;
        if (Tcp < 8) Tcp = 8;
        if (m == 0) {
            const int pos = __popc(bal & ((1u << tid) - 1u));
            stl[pos] = tid;
        }
        const unsigned mb = ~bal;
        const int firstMasked = mb ? (__ffs(mb) - 1) : 0;
        if (tid >= Tc) stl[tid] = firstMasked;
        scs[tid] = (tid < Tc) ? 0.0f : -CUDART_INF_F;
        if (tid == 0) sjm = Tcp >> 3;
    }
    __syncthreads();

    // gather compact values rows (permutation within 128B lines -> coalesced)
    const float* gvb = g_values + (size_t)b * DH_ * T_;
#pragma unroll
    for (int i = 0; i < 16; i++) {
        const int f = tid + 256 * i;
        svf[f] = gvb[(f & ~31) + stl[f & 31]];
    }
    __syncthreads();

    const int jm = sjm;

    const float4* qb =
        reinterpret_cast<const float4*>(img + (size_t)b * DH_ * N_ + n0);
    float* wb = scoef + warp * (64 * 33);
    float* ogc =
        out_coef + ((size_t)b * N_ + blockIdx.x * 512 + warp * 64) * T_;
    float* oa = out_attn + (size_t)b * DH_ * N_ + n0 + 2 * half;
    const ulonglong2* sv = reinterpret_cast<const ulonglong2*>(svf);

    if (jm == 2)
        attn_core<2>(sv, scs, stl, qb, wb, ogc, oa, half, pair, lane);
    else if (jm == 3)
        attn_core<3>(sv, scs, stl, qb, wb, ogc, oa, half, pair, lane);
    else if (jm == 4)
        attn_core<4>(sv, scs, stl, qb, wb, ogc, oa, half, pair, lane);
    else
        attn_core<1>(sv, scs, stl, qb, wb, ogc, oa, half, pair, lane);
}

extern "C" void kernel_launch(void* const* d_in, const int* in_sizes, int n_in,
                              void* d_out, int out_size) {
    const float* wf   = (const float*)d_in[0];
    const float* img  = (const float*)d_in[1];
    const int*   msk  = (const int*)d_in[2];
    const float* Wm   = (const float*)d_in[3];
    const float* bias = (const float*)d_in[4];

    float* out_attn = (float*)d_out;
    float* out_coef = (float*)d_out + (size_t)B_ * DH_ * N_;

    dim3 vgrid(4, B_);
    values_kernel<<<vgrid, 256>>>(wf, Wm, bias);

    dim3 grid(N_ / 512, B_);
    attn_kernel<<<grid, 256>>>(img, msk, out_attn, out_coef);
}

// round 16
// speedup vs baseline: 1.5230x; 1.0202x over previous
#include <cuda_runtime.h>
#include <math_constants.h>
#include <cstdint>

// Shapes (fixed):
//   word_features  [B, D, T]   = [32, 256, 32]   fp32   d_in[0]
//   image_features [B, Dh,H,W] = [32, 128,128,128] fp32 d_in[1]
//   words_mask     [B, T]      = [32, 32]        int32  d_in[2]
//   W              [Dh, D]     = [128, 256]      fp32   d_in[3]
//   b              [Dh]        = [128]           fp32   d_in[4]
// Outputs: attn [B,Dh,N] at 0, attn_coefficients [B,N,T] at B*Dh*N.
//
// R15 core (155.4us) + (a) PDL overlap of values_kernel with attn preamble,
// (b) coef copy-out interleaved into phase 3's FFMA2 stream.

#define B_   32
#define D_   256
#define T_   32
#define DH_  128
#define N_   16384

__device__ float g_values[B_ * DH_ * T_];

// ---------------- packed f32x2 helpers ----------------
__device__ __forceinline__ unsigned long long pk2(float lo, float hi) {
    unsigned long long r;
    asm("mov.b64 %0, {%1, %2};" : "=l"(r) : "f"(lo), "f"(hi));
    return r;
}
__device__ __forceinline__ float2 unpk2(unsigned long long v) {
    float2 f;
    asm("mov.b64 {%0, %1}, %2;" : "=f"(f.x), "=f"(f.y) : "l"(v));
    return f;
}
__device__ __forceinline__ unsigned long long ffma2(unsigned long long a,
                                                    unsigned long long b,
                                                    unsigned long long c) {
    unsigned long long d;
    asm("fma.rn.f32x2 %0, %1, %2, %3;" : "=l"(d) : "l"(a), "l"(b), "l"(c));
    return d;
}
__device__ __forceinline__ unsigned long long add2(unsigned long long a,
                                                   unsigned long long b) {
    unsigned long long d;
    asm("add.rn.f32x2 %0, %1, %2;" : "=l"(d) : "l"(a), "l"(b));
    return d;
}

// ---------------- kernel 1: values = W * wf + b ----------------
#define SW_PAD 264
__global__ __launch_bounds__(256)
void values_kernel(const float* __restrict__ wf,
                   const float* __restrict__ Wm,
                   const float* __restrict__ bias) {
    __shared__ float swf[D_ * T_];
    __shared__ float sW[32 * SW_PAD];
    const int c = blockIdx.x;
    const int b = blockIdx.y;
    const int tid = threadIdx.x;

    {
        const float4* src =
            reinterpret_cast<const float4*>(wf + (size_t)b * D_ * T_);
        float4* dst = reinterpret_cast<float4*>(swf);
#pragma unroll
        for (int i = 0; i < 8; i++) dst[tid + 256 * i] = src[tid + 256 * i];

        const float4* wsrc =
            reinterpret_cast<const float4*>(Wm + (size_t)c * 32 * D_);
#pragma unroll
        for (int i = 0; i < 8; i++) {
            const int idx = tid + 256 * i;
            const int kl = idx >> 6;
            const int dc = idx & 63;
            float4 v = wsrc[idx];
            *reinterpret_cast<float4*>(&sW[kl * SW_PAD + dc * 4]) = v;
        }
    }
    __syncthreads();

    const int k_l = tid >> 3;
    const int tq = tid & 7;
    const int k = c * 32 + k_l;

    const float bk = bias[k];
    unsigned long long acc0 = pk2(bk, bk);
    unsigned long long acc1 = pk2(bk, bk);

#pragma unroll 4
    for (int d = 0; d < D_; d++) {
        const float w = sW[k_l * SW_PAD + d];
        const unsigned long long wp = pk2(w, w);
        const ulonglong2 v =
            *reinterpret_cast<const ulonglong2*>(&swf[d * T_ + tq * 4]);
        acc0 = ffma2(wp, v.x, acc0);
        acc1 = ffma2(wp, v.y, acc1);
    }

    ulonglong2 o;
    o.x = acc0;
    o.y = acc1;
    *reinterpret_cast<ulonglong2*>(
        g_values + ((size_t)b * DH_ + k) * T_ + tq * 4) = o;
}

// ---------------- templated attention core (JM = Tcp/8, 1..4) ----------------
// Lane pair (2p,2p+1) shares 4 pixels; even lane owns compact cols
// [0, 4*JM), odd lane [4*JM, 8*JM). Coefficients staged in padded per-warp
// smem scratch; copy-out interleaved into phase 3.
template <int JM>
__device__ __forceinline__ void attn_core(
    const ulonglong2* __restrict__ svals,
    const float* __restrict__ scs,
    const int* __restrict__ stl,
    const float4* __restrict__ qb,
    float* __restrict__ wb,    // per-warp coef scratch (64*33 floats)
    float* __restrict__ ogc,   // out_coef warp base (64 rows x 32 floats)
    float* __restrict__ oa,    // out_attn + b*Dh*N + n0 + 2*half
    const int half, const int pair, const int lane) {
    constexpr int NJ = 2 * JM;
    constexpr int PF = (JM <= 2) ? 8 : 4;  // q prefetch depth
    const int cb = half * 4 * JM;

    // zero the warp's coef scratch (2112 floats = 528 float4)
    {
        const float4 z4 = make_float4(0.f, 0.f, 0.f, 0.f);
        float4* wz = reinterpret_cast<float4*>(wb);
        for (int i = lane; i < 528; i += 32) wz[i] = z4;
    }

    unsigned long long acc[4][NJ];
#pragma unroll
    for (int px = 0; px < 4; px++)
#pragma unroll
        for (int j = 0; j < NJ; j++) acc[px][j] = 0ULL;

    // ---- phase 1: S_compact = sum_k q * vals_compact ----
    float4 qv[PF];
#pragma unroll
    for (int kk = 0; kk < PF; kk++) qv[kk] = qb[(size_t)kk * (N_ / 4)];

    for (int k = 0; k < DH_; k += PF) {
        float4 qn[PF];
        if (k + PF < DH_) {
#pragma unroll
            for (int kk = 0; kk < PF; kk++)
                qn[kk] = qb[(size_t)(k + PF + kk) * (N_ / 4)];
        }
#pragma unroll
        for (int kk = 0; kk < PF; kk++) {
            const unsigned long long q0 = pk2(qv[kk].x, qv[kk].x);
            const unsigned long long q1 = pk2(qv[kk].y, qv[kk].y);
            const unsigned long long q2 = pk2(qv[kk].z, qv[kk].z);
            const unsigned long long q3 = pk2(qv[kk].w, qv[kk].w);
            const ulonglong2* vr = &svals[(size_t)(k + kk) * 8 + half * JM];
#pragma unroll
            for (int j = 0; j < JM; j++) {
                const ulonglong2 v = vr[j];
                acc[0][2 * j + 0] = ffma2(q0, v.x, acc[0][2 * j + 0]);
                acc[0][2 * j + 1] = ffma2(q0, v.y, acc[0][2 * j + 1]);
                acc[1][2 * j + 0] = ffma2(q1, v.x, acc[1][2 * j + 0]);
                acc[1][2 * j + 1] = ffma2(q1, v.y, acc[1][2 * j + 1]);
                acc[2][2 * j + 0] = ffma2(q2, v.x, acc[2][2 * j + 0]);
                acc[2][2 * j + 1] = ffma2(q2, v.y, acc[2][2 * j + 1]);
                acc[3][2 * j + 0] = ffma2(q3, v.x, acc[3][2 * j + 0]);
                acc[3][2 * j + 1] = ffma2(q3, v.y, acc[3][2 * j + 1]);
            }
        }
#pragma unroll
        for (int kk = 0; kk < PF; kk++) qv[kk] = qn[kk];
    }

    // ---- phase 2: softmax over compact cols (pads -> -inf -> 0) ----
#pragma unroll
    for (int px = 0; px < 4; px++) {
        const unsigned long long* snp =
            reinterpret_cast<const unsigned long long*>(&scs[cb]);
        float Sv[2 * NJ];
#pragma unroll
        for (int j = 0; j < NJ; j++) {
            const float2 f = unpk2(add2(acc[px][j], snp[j]));
            Sv[2 * j + 0] = f.x;
            Sv[2 * j + 1] = f.y;
        }
        float m = -CUDART_INF_F;
#pragma unroll
        for (int i = 0; i < 2 * NJ; i++) m = fmaxf(m, Sv[i]);
        m = fmaxf(m, __shfl_xor_sync(0xffffffffu, m, 1));
        float sum = 0.f;
#pragma unroll
        for (int i = 0; i < 2 * NJ; i++) {
            Sv[i] = __expf(Sv[i] - m);
            sum += Sv[i];
        }
        sum += __shfl_xor_sync(0xffffffffu, sum, 1);
        const float inv = 1.0f / sum;
#pragma unroll
        for (int i = 0; i < 2 * NJ; i++) Sv[i] *= inv;
#pragma unroll
        for (int j = 0; j < NJ; j++)
            acc[px][j] = pk2(Sv[2 * j], Sv[2 * j + 1]);
    }

    // ---- scatter coefficients into smem scratch (pads write exact 0) ----
    __syncwarp();  // order scratch zeroing before scatter
#pragma unroll
    for (int px = 0; px < 4; px++) {
        float* r = wb + (pair * 4 + px) * 33;
#pragma unroll
        for (int j = 0; j < NJ; j++) {
            const float2 f = unpk2(acc[px][j]);
            r[stl[cb + 2 * j + 0]] = f.x;
            r[stl[cb + 2 * j + 1]] = f.y;
        }
    }
    __syncwarp();  // scatter visible to all lanes before copy-out

    // ---- phase 3 with interleaved coef copy-out ----
    float4* og4 = reinterpret_cast<float4*>(ogc);
    for (int kc = 0; kc < 32; kc++) {
        const int k = kc * 4;
        unsigned long long mine[4], sent[4];
#pragma unroll
        for (int kk = 0; kk < 4; kk++) {
            const ulonglong2* vr = &svals[(size_t)(k + kk) * 8 + half * JM];
            unsigned long long a0 = 0ULL, a1 = 0ULL, a2 = 0ULL, a3 = 0ULL;
#pragma unroll
            for (int j = 0; j < JM; j++) {
                const ulonglong2 v = vr[j];
                a0 = ffma2(v.x, acc[0][2 * j + 0], a0);
                a0 = ffma2(v.y, acc[0][2 * j + 1], a0);
                a1 = ffma2(v.x, acc[1][2 * j + 0], a1);
                a1 = ffma2(v.y, acc[1][2 * j + 1], a1);
                a2 = ffma2(v.x, acc[2][2 * j + 0], a2);
                a2 = ffma2(v.y, acc[2][2 * j + 1], a2);
                a3 = ffma2(v.x, acc[3][2 * j + 0], a3);
                a3 = ffma2(v.y, acc[3][2 * j + 1], a3);
            }
            const float2 f0 = unpk2(a0), f1 = unpk2(a1);
            const float2 f2 = unpk2(a2), f3 = unpk2(a3);
            const unsigned long long p01 = pk2(f0.x + f0.y, f1.x + f1.y);
            const unsigned long long p23 = pk2(f2.x + f2.y, f3.x + f3.y);
            sent[kk] = half ? p01 : p23;
            mine[kk] = half ? p23 : p01;
        }
        unsigned long long got[4];
#pragma unroll
        for (int kk = 0; kk < 4; kk++)
            got[kk] = __shfl_xor_sync(0xffffffffu, sent[kk], 1);
#pragma unroll
        for (int kk = 0; kk < 4; kk++) {
            const float2 r = unpk2(add2(mine[kk], got[kk]));
            *reinterpret_cast<float2*>(oa + (size_t)(k + kk) * N_) =
                make_float2(r.x, r.y);
        }
        // interleaved coef copy-out (16 iterations over first 16 chunks)
        if (kc < 16) {
            const int i16 = kc * 32 + lane;
            const int row = i16 >> 3;
            const int c4 = (i16 & 7) * 4;
            const float* rp = wb + row * 33 + c4;
            float4 v;
            v.x = rp[0];
            v.y = rp[1];
            v.z = rp[2];
            v.w = rp[3];
            og4[i16] = v;
        }
    }
}

// ---------------- kernel 2: in-CTA compaction + gather + dispatch ----------------
__global__ __launch_bounds__(256, 2)
void attn_kernel(const float* __restrict__ img,
                 const int* __restrict__ mask,
                 float* __restrict__ out_attn,
                 float* __restrict__ out_coef) {
    __shared__ __align__(16) float svf[DH_ * T_];
    __shared__ __align__(8) float scs[T_];
    __shared__ int stl[T_];
    __shared__ int sjm;
    __shared__ __align__(16) float scoef[8 * 64 * 33];  // 8 warps x 8448B

    const int b = blockIdx.y;
    const int tid = threadIdx.x;
    const int lane = tid & 31;
    const int warp = tid >> 5;
    const int half = lane & 1;
    const int pair = lane >> 1;
    const int n0 = blockIdx.x * 512 + warp * 64 + pair * 4;

    // in-CTA mask compaction (warp 0) — independent of values_kernel output
    if (tid < 32) {
        const int m = mask[b * T_ + tid];
        const unsigned bal = __ballot_sync(0xffffffffu, m == 0);
        const int Tc = __popc(bal);
        int Tcp = (Tc + 7) & ~7;
        if (Tcp < 8) Tcp = 8;
        if (m == 0) {
            const int pos = __popc(bal & ((1u << tid) - 1u));
            stl[pos] = tid;
        }
        const unsigned mb = ~bal;
        const int firstMasked = mb ? (__ffs(mb) - 1) : 0;
        if (tid >= Tc) stl[tid] = firstMasked;
        scs[tid] = (tid < Tc) ? 0.0f : -CUDART_INF_F;
        if (tid == 0) sjm = Tcp >> 3;
    }

    // PDL: wait for values_kernel's g_values to be globally visible
    cudaGridDependencySynchronize();
    __syncthreads();

    // gather compact values rows (permutation within 128B lines -> coalesced)
    const float* gvb = g_values + (size_t)b * DH_ * T_;
#pragma unroll
    for (int i = 0; i < 16; i++) {
        const int f = tid + 256 * i;
        svf[f] = gvb[(f & ~31) + stl[f & 31]];
    }
    __syncthreads();

    const int jm = sjm;

    const float4* qb =
        reinterpret_cast<const float4*>(img + (size_t)b * DH_ * N_ + n0);
    float* wb = scoef + warp * (64 * 33);
    float* ogc =
        out_coef + ((size_t)b * N_ + blockIdx.x * 512 + warp * 64) * T_;
    float* oa = out_attn + (size_t)b * DH_ * N_ + n0 + 2 * half;
    const ulonglong2* sv = reinterpret_cast<const ulonglong2*>(svf);

    if (jm == 2)
        attn_core<2>(sv, scs, stl, qb, wb, ogc, oa, half, pair, lane);
    else if (jm == 3)
        attn_core<3>(sv, scs, stl, qb, wb, ogc, oa, half, pair, lane);
    else if (jm == 4)
        attn_core<4>(sv, scs, stl, qb, wb, ogc, oa, half, pair, lane);
    else
        attn_core<1>(sv, scs, stl, qb, wb, ogc, oa, half, pair, lane);
}

extern "C" void kernel_launch(void* const* d_in, const int* in_sizes, int n_in,
                              void* d_out, int out_size) {
    const float* wf   = (const float*)d_in[0];
    const float* img  = (const float*)d_in[1];
    const int*   msk  = (const int*)d_in[2];
    const float* Wm   = (const float*)d_in[3];
    const float* bias = (const float*)d_in[4];

    float* out_attn = (float*)d_out;
    float* out_coef = (float*)d_out + (size_t)B_ * DH_ * N_;

    dim3 vgrid(4, B_);
    values_kernel<<<vgrid, 256>>>(wf, Wm, bias);

    dim3 grid(N_ / 512, B_);

    // PDL launch: attn starts during values_kernel; it waits on
    // cudaGridDependencySynchronize() before reading g_values.
    cudaLaunchConfig_t cfg = {};
    cfg.gridDim = grid;
    cfg.blockDim = dim3(256, 1, 1);
    cfg.dynamicSmemBytes = 0;
    cudaLaunchAttribute attrs[1];
    attrs[0].id = cudaLaunchAttributeProgrammaticStreamSerialization;
    attrs[0].val.programmaticStreamSerializationAllowed = 1;
    cfg.attrs = attrs;
    cfg.numAttrs = 1;
    cudaError_t e =
        cudaLaunchKernelEx(&cfg, attn_kernel, img, msk, out_attn, out_coef);
    if (e != cudaSuccess) {
        // fallback: plain serialized launch (still correct)
        attn_kernel<<<grid, 256>>>(img, msk, out_attn, out_coef);
    }
}

// round 17
// speedup vs baseline: 1.5253x; 1.0015x over previous
#include <cuda_runtime.h>
#include <math_constants.h>
#include <cstdint>

// Shapes (fixed):
//   word_features  [B, D, T]   = [32, 256, 32]   fp32   d_in[0]
//   image_features [B, Dh,H,W] = [32, 128,128,128] fp32 d_in[1]
//   words_mask     [B, T]      = [32, 32]        int32  d_in[2]
//   W              [Dh, D]     = [128, 256]      fp32   d_in[3]
//   b              [Dh]        = [128]           fp32   d_in[4]
// Outputs: attn [B,Dh,N] at 0, attn_coefficients [B,N,T] at B*Dh*N.
//
// R16 (152.3us) + strength-reduced addressing: all hot-loop global/shared
// accesses use a single bumped byte pointer with compile-time immediate
// offsets (kills IMAD address chains competing with FFMA2 for issue).

#define B_   32
#define D_   256
#define T_   32
#define DH_  128
#define N_   16384

#define QSTRIDE 65536UL  // one k-step of img/attn in bytes: N_*4

__device__ float g_values[B_ * DH_ * T_];

// ---------------- packed f32x2 helpers ----------------
__device__ __forceinline__ unsigned long long pk2(float lo, float hi) {
    unsigned long long r;
    asm("mov.b64 %0, {%1, %2};" : "=l"(r) : "f"(lo), "f"(hi));
    return r;
}
__device__ __forceinline__ float2 unpk2(unsigned long long v) {
    float2 f;
    asm("mov.b64 {%0, %1}, %2;" : "=f"(f.x), "=f"(f.y) : "l"(v));
    return f;
}
__device__ __forceinline__ unsigned long long ffma2(unsigned long long a,
                                                    unsigned long long b,
                                                    unsigned long long c) {
    unsigned long long d;
    asm("fma.rn.f32x2 %0, %1, %2, %3;" : "=l"(d) : "l"(a), "l"(b), "l"(c));
    return d;
}
__device__ __forceinline__ unsigned long long add2(unsigned long long a,
                                                   unsigned long long b) {
    unsigned long long d;
    asm("add.rn.f32x2 %0, %1, %2;" : "=l"(d) : "l"(a), "l"(b));
    return d;
}

// ---------------- kernel 1: values = W * wf + b ----------------
#define SW_PAD 264
__global__ __launch_bounds__(256)
void values_kernel(const float* __restrict__ wf,
                   const float* __restrict__ Wm,
                   const float* __restrict__ bias) {
    __shared__ float swf[D_ * T_];
    __shared__ float sW[32 * SW_PAD];
    const int c = blockIdx.x;
    const int b = blockIdx.y;
    const int tid = threadIdx.x;

    {
        const float4* src =
            reinterpret_cast<const float4*>(wf + (size_t)b * D_ * T_);
        float4* dst = reinterpret_cast<float4*>(swf);
#pragma unroll
        for (int i = 0; i < 8; i++) dst[tid + 256 * i] = src[tid + 256 * i];

        const float4* wsrc =
            reinterpret_cast<const float4*>(Wm + (size_t)c * 32 * D_);
#pragma unroll
        for (int i = 0; i < 8; i++) {
            const int idx = tid + 256 * i;
            const int kl = idx >> 6;
            const int dc = idx & 63;
            float4 v = wsrc[idx];
            *reinterpret_cast<float4*>(&sW[kl * SW_PAD + dc * 4]) = v;
        }
    }
    __syncthreads();

    const int k_l = tid >> 3;
    const int tq = tid & 7;
    const int k = c * 32 + k_l;

    const float bk = bias[k];
    unsigned long long acc0 = pk2(bk, bk);
    unsigned long long acc1 = pk2(bk, bk);

#pragma unroll 4
    for (int d = 0; d < D_; d++) {
        const float w = sW[k_l * SW_PAD + d];
        const unsigned long long wp = pk2(w, w);
        const ulonglong2 v =
            *reinterpret_cast<const ulonglong2*>(&swf[d * T_ + tq * 4]);
        acc0 = ffma2(wp, v.x, acc0);
        acc1 = ffma2(wp, v.y, acc1);
    }

    ulonglong2 o;
    o.x = acc0;
    o.y = acc1;
    *reinterpret_cast<ulonglong2*>(
        g_values + ((size_t)b * DH_ + k) * T_ + tq * 4) = o;
}

// ---------------- templated attention core (JM = Tcp/8, 1..4) ----------------
template <int JM>
__device__ __forceinline__ void attn_core(
    const char* __restrict__ svb,  // byte ptr: svals base + half*JM*16
    const float* __restrict__ scs,
    const int* __restrict__ stl,
    const char* __restrict__ qp0,  // byte ptr: img + b*Dh*N + n0
    float* __restrict__ wb,        // per-warp coef scratch (64*33 floats)
    float* __restrict__ ogc,       // out_coef warp base
    char* __restrict__ oap,        // byte ptr: out_attn + ... + 2*half
    const int half, const int pair, const int lane) {
    constexpr int NJ = 2 * JM;
    constexpr int PF = (JM <= 2) ? 8 : 4;  // q prefetch depth
    const int cb = half * 4 * JM;

    // zero the warp's coef scratch (2112 floats = 528 float4)
    {
        const float4 z4 = make_float4(0.f, 0.f, 0.f, 0.f);
        float4* wz = reinterpret_cast<float4*>(wb);
        for (int i = lane; i < 528; i += 32) wz[i] = z4;
    }

    unsigned long long acc[4][NJ];
#pragma unroll
    for (int px = 0; px < 4; px++)
#pragma unroll
        for (int j = 0; j < NJ; j++) acc[px][j] = 0ULL;

    // ---- phase 1: S_compact = sum_k q * vals_compact ----
    const char* qp = qp0;
    const char* sp = svb;  // bumped by PF*128 per iteration

    float4 qv[PF];
#pragma unroll
    for (int kk = 0; kk < PF; kk++)
        qv[kk] = *reinterpret_cast<const float4*>(qp + kk * QSTRIDE);

    for (int k = 0; k < DH_; k += PF) {
        float4 qn[PF];
        if (k + PF < DH_) {
#pragma unroll
            for (int kk = 0; kk < PF; kk++)
                qn[kk] = *reinterpret_cast<const float4*>(
                    qp + (PF + kk) * QSTRIDE);
        }
#pragma unroll
        for (int kk = 0; kk < PF; kk++) {
            const unsigned long long q0 = pk2(qv[kk].x, qv[kk].x);
            const unsigned long long q1 = pk2(qv[kk].y, qv[kk].y);
            const unsigned long long q2 = pk2(qv[kk].z, qv[kk].z);
            const unsigned long long q3 = pk2(qv[kk].w, qv[kk].w);
#pragma unroll
            for (int j = 0; j < JM; j++) {
                const ulonglong2 v = *reinterpret_cast<const ulonglong2*>(
                    sp + kk * 128 + j * 16);
                acc[0][2 * j + 0] = ffma2(q0, v.x, acc[0][2 * j + 0]);
                acc[0][2 * j + 1] = ffma2(q0, v.y, acc[0][2 * j + 1]);
                acc[1][2 * j + 0] = ffma2(q1, v.x, acc[1][2 * j + 0]);
                acc[1][2 * j + 1] = ffma2(q1, v.y, acc[1][2 * j + 1]);
                acc[2][2 * j + 0] = ffma2(q2, v.x, acc[2][2 * j + 0]);
                acc[2][2 * j + 1] = ffma2(q2, v.y, acc[2][2 * j + 1]);
                acc[3][2 * j + 0] = ffma2(q3, v.x, acc[3][2 * j + 0]);
                acc[3][2 * j + 1] = ffma2(q3, v.y, acc[3][2 * j + 1]);
            }
        }
#pragma unroll
        for (int kk = 0; kk < PF; kk++) qv[kk] = qn[kk];
        qp += PF * QSTRIDE;
        sp += PF * 128;
    }

    // ---- phase 2: softmax over compact cols (pads -> -inf -> 0) ----
#pragma unroll
    for (int px = 0; px < 4; px++) {
        const unsigned long long* snp =
            reinterpret_cast<const unsigned long long*>(&scs[cb]);
        float Sv[2 * NJ];
#pragma unroll
        for (int j = 0; j < NJ; j++) {
            const float2 f = unpk2(add2(acc[px][j], snp[j]));
            Sv[2 * j + 0] = f.x;
            Sv[2 * j + 1] = f.y;
        }
        float m = -CUDART_INF_F;
#pragma unroll
        for (int i = 0; i < 2 * NJ; i++) m = fmaxf(m, Sv[i]);
        m = fmaxf(m, __shfl_xor_sync(0xffffffffu, m, 1));
        float sum = 0.f;
#pragma unroll
        for (int i = 0; i < 2 * NJ; i++) {
            Sv[i] = __expf(Sv[i] - m);
            sum += Sv[i];
        }
        sum += __shfl_xor_sync(0xffffffffu, sum, 1);
        const float inv = 1.0f / sum;
#pragma unroll
        for (int i = 0; i < 2 * NJ; i++) Sv[i] *= inv;
#pragma unroll
        for (int j = 0; j < NJ; j++)
            acc[px][j] = pk2(Sv[2 * j], Sv[2 * j + 1]);
    }

    // ---- scatter coefficients into smem scratch (pads write exact 0) ----
    __syncwarp();  // order scratch zeroing before scatter
#pragma unroll
    for (int px = 0; px < 4; px++) {
        float* r = wb + (pair * 4 + px) * 33;
#pragma unroll
        for (int j = 0; j < NJ; j++) {
            const float2 f = unpk2(acc[px][j]);
            r[stl[cb + 2 * j + 0]] = f.x;
            r[stl[cb + 2 * j + 1]] = f.y;
        }
    }
    __syncwarp();  // scatter visible to all lanes before copy-out

    // ---- phase 3 with interleaved coef copy-out ----
    float4* og4 = reinterpret_cast<float4*>(ogc);
    const char* s3 = svb;  // bumped by 512 per chunk
    char* op = oap;        // bumped by 4*QSTRIDE per chunk
    for (int kc = 0; kc < 32; kc++) {
        unsigned long long mine[4], sent[4];
#pragma unroll
        for (int kk = 0; kk < 4; kk++) {
            unsigned long long a0 = 0ULL, a1 = 0ULL, a2 = 0ULL, a3 = 0ULL;
#pragma unroll
            for (int j = 0; j < JM; j++) {
                const ulonglong2 v = *reinterpret_cast<const ulonglong2*>(
                    s3 + kk * 128 + j * 16);
                a0 = ffma2(v.x, acc[0][2 * j + 0], a0);
                a0 = ffma2(v.y, acc[0][2 * j + 1], a0);
                a1 = ffma2(v.x, acc[1][2 * j + 0], a1);
                a1 = ffma2(v.y, acc[1][2 * j + 1], a1);
                a2 = ffma2(v.x, acc[2][2 * j + 0], a2);
                a2 = ffma2(v.y, acc[2][2 * j + 1], a2);
                a3 = ffma2(v.x, acc[3][2 * j + 0], a3);
                a3 = ffma2(v.y, acc[3][2 * j + 1], a3);
            }
            const float2 f0 = unpk2(a0), f1 = unpk2(a1);
            const float2 f2 = unpk2(a2), f3 = unpk2(a3);
            const unsigned long long p01 = pk2(f0.x + f0.y, f1.x + f1.y);
            const unsigned long long p23 = pk2(f2.x + f2.y, f3.x + f3.y);
            sent[kk] = half ? p01 : p23;
            mine[kk] = half ? p23 : p01;
        }
        unsigned long long got[4];
#pragma unroll
        for (int kk = 0; kk < 4; kk++)
            got[kk] = __shfl_xor_sync(0xffffffffu, sent[kk], 1);
#pragma unroll
        for (int kk = 0; kk < 4; kk++) {
            const float2 r = unpk2(add2(mine[kk], got[kk]));
            *reinterpret_cast<float2*>(op + kk * QSTRIDE) =
                make_float2(r.x, r.y);
        }
        // interleaved coef copy-out (16 iterations over first 16 chunks)
        if (kc < 16) {
            const int i16 = kc * 32 + lane;
            const int row = i16 >> 3;
            const int c4 = (i16 & 7) * 4;
            const float* rp = wb + row * 33 + c4;
            float4 v;
            v.x = rp[0];
            v.y = rp[1];
            v.z = rp[2];
            v.w = rp[3];
            og4[i16] = v;
        }
        s3 += 512;
        op += 4 * QSTRIDE;
    }
}

// ---------------- kernel 2: in-CTA compaction + gather + dispatch ----------------
__global__ __launch_bounds__(256, 2)
void attn_kernel(const float* __restrict__ img,
                 const int* __restrict__ mask,
                 float* __restrict__ out_attn,
                 float* __restrict__ out_coef) {
    __shared__ __align__(16) float svf[DH_ * T_];
    __shared__ __align__(8) float scs[T_];
    __shared__ int stl[T_];
    __shared__ int sjm;
    __shared__ __align__(16) float scoef[8 * 64 * 33];  // 8 warps x 8448B

    const int b = blockIdx.y;
    const int tid = threadIdx.x;
    const int lane = tid & 31;
    const int warp = tid >> 5;
    const int half = lane & 1;
    const int pair = lane >> 1;
    const int n0 = blockIdx.x * 512 + warp * 64 + pair * 4;

    // in-CTA mask compaction (warp 0) — independent of values_kernel output
    if (tid < 32) {
        const int m = mask[b * T_ + tid];
        const unsigned bal = __ballot_sync(0xffffffffu, m == 0);
        const int Tc = __popc(bal);
        int Tcp = (Tc + 7) & ~7;
        if (Tcp < 8) Tcp = 8;
        if (m == 0) {
            const int pos = __popc(bal & ((1u << tid) - 1u));
            stl[pos] = tid;
        }
        const unsigned mb = ~bal;
        const int firstMasked = mb ? (__ffs(mb) - 1) : 0;
        if (tid >= Tc) stl[tid] = firstMasked;
        scs[tid] = (tid < Tc) ? 0.0f : -CUDART_INF_F;
        if (tid == 0) sjm = Tcp >> 3;
    }

    // PDL: wait for values_kernel's g_values to be globally visible
    cudaGridDependencySynchronize();
    __syncthreads();

    // gather compact values rows (permutation within 128B lines -> coalesced)
    const float* gvb = g_values + (size_t)b * DH_ * T_;
#pragma unroll
    for (int i = 0; i < 16; i++) {
        const int f = tid + 256 * i;
        svf[f] = gvb[(f & ~31) + stl[f & 31]];
    }
    __syncthreads();

    const int jm = sjm;

    const char* qp0 = reinterpret_cast<const char*>(
        img + (size_t)b * DH_ * N_ + n0);
    float* wb = scoef + warp * (64 * 33);
    float* ogc =
        out_coef + ((size_t)b * N_ + blockIdx.x * 512 + warp * 64) * T_;
    char* oap = reinterpret_cast<char*>(
        out_attn + (size_t)b * DH_ * N_ + n0 + 2 * half);
    const char* svb0 = reinterpret_cast<const char*>(svf);

    if (jm == 2)
        attn_core<2>(svb0 + half * 2 * 16, scs, stl, qp0, wb, ogc, oap, half,
                     pair, lane);
    else if (jm == 3)
        attn_core<3>(svb0 + half * 3 * 16, scs, stl, qp0, wb, ogc, oap, half,
                     pair, lane);
    else if (jm == 4)
        attn_core<4>(svb0 + half * 4 * 16, scs, stl, qp0, wb, ogc, oap, half,
                     pair, lane);
    else
        attn_core<1>(svb0 + half * 1 * 16, scs, stl, qp0, wb, ogc, oap, half,
                     pair, lane);
}

extern "C" void kernel_launch(void* const* d_in, const int* in_sizes, int n_in,
                              void* d_out, int out_size) {
    const float* wf   = (const float*)d_in[0];
    const float* img  = (const float*)d_in[1];
    const int*   msk  = (const int*)d_in[2];
    const float* Wm   = (const float*)d_in[3];
    const float* bias = (const float*)d_in[4];

    float* out_attn = (float*)d_out;
    float* out_coef = (float*)d_out + (size_t)B_ * DH_ * N_;

    dim3 vgrid(4, B_);
    values_kernel<<<vgrid, 256>>>(wf, Wm, bias);

    dim3 grid(N_ / 512, B_);

    // PDL launch: attn starts during values_kernel; it waits on
    // cudaGridDependencySynchronize() before reading g_values.
    cudaLaunchConfig_t cfg = {};
    cfg.gridDim = grid;
    cfg.blockDim = dim3(256, 1, 1);
    cfg.dynamicSmemBytes = 0;
    cudaLaunchAttribute attrs[1];
    attrs[0].id = cudaLaunchAttributeProgrammaticStreamSerialization;
    attrs[0].val.programmaticStreamSerializationAllowed = 1;
    cfg.attrs = attrs;
    cfg.numAttrs = 1;
    cudaError_t e =
        cudaLaunchKernelEx(&cfg, attn_kernel, img, msk, out_attn, out_coef);
    if (e != cudaSuccess) {
        // fallback: plain serialized launch (still correct)
        attn_kernel<<<grid, 256>>>(img, msk, out_attn, out_coef);
    }
}